// round 16
// baseline (speedup 1.0000x reference)
#include <cuda_runtime.h>

typedef unsigned long long u64;

#define TSEQ 64
#define NB 2048
#define FULLM 0xffffffffu

// ---------------- packed fp32x2 + MUFU helpers ----------------
__device__ __forceinline__ u64 ffma2(u64 a, u64 b, u64 c) {
    u64 d; asm("fma.rn.f32x2 %0, %1, %2, %3;" : "=l"(d) : "l"(a), "l"(b), "l"(c)); return d;
}
__device__ __forceinline__ u64 fmul2(u64 a, u64 b) {
    u64 d; asm("mul.rn.f32x2 %0, %1, %2;" : "=l"(d) : "l"(a), "l"(b)); return d;
}
__device__ __forceinline__ u64 fadd2(u64 a, u64 b) {
    u64 d; asm("add.rn.f32x2 %0, %1, %2;" : "=l"(d) : "l"(a), "l"(b)); return d;
}
__device__ __forceinline__ float2 unpk2(u64 a) {
    float lo, hi; asm("mov.b64 {%0, %1}, %2;" : "=f"(lo), "=f"(hi) : "l"(a));
    return make_float2(lo, hi);
}
__device__ __forceinline__ u64 pk2(float lo, float hi) {
    u64 d; asm("mov.b64 %0, {%1, %2};" : "=l"(d) : "f"(lo), "f"(hi)); return d;
}
__device__ __forceinline__ float ex2a(float x){ float r; asm("ex2.approx.f32 %0, %1;" : "=f"(r) : "f"(x)); return r; }
__device__ __forceinline__ float rcpa(float x){ float r; asm("rcp.approx.f32 %0, %1;" : "=f"(r) : "f"(x)); return r; }
__device__ __forceinline__ float lg2a(float x){ float r; asm("lg2.approx.f32 %0, %1;" : "=f"(r) : "f"(x)); return r; }

#define TWO_LOG2E 2.885390081777927f

__device__ __forceinline__ float tanh_pre(float z, float bs){
    float e = ex2a(fmaf(z, TWO_LOG2E, bs));
    return fmaf(-2.0f, rcpa(e + 1.0f), 1.0f);
}
__device__ __forceinline__ float fast_tanh(float x){
    float e = ex2a(x * TWO_LOG2E);
    return fmaf(-2.0f, rcpa(e + 1.0f), 1.0f);
}
__device__ __forceinline__ float fast_sigmoid(float x){
    float e = ex2a(x * -1.4426950408889634f);
    return rcpa(e + 1.0f);
}

// ---- ordered smem primitives (converged-warp STS->LDS, asm-ordered) ----
__device__ __forceinline__ void sts32(unsigned a, float v){
    asm volatile("st.shared.b32 [%0], %1;" :: "r"(a), "f"(v) : "memory");
}
__device__ __forceinline__ void lds_v16(unsigned a, u64* v){
    asm volatile("ld.shared.v2.b64 {%0,%1}, [%2];"    : "=l"(v[0]), "=l"(v[1]) : "r"(a) : "memory");
    asm volatile("ld.shared.v2.b64 {%0,%1}, [%2+16];" : "=l"(v[2]), "=l"(v[3]) : "r"(a) : "memory");
    asm volatile("ld.shared.v2.b64 {%0,%1}, [%2+32];" : "=l"(v[4]), "=l"(v[5]) : "r"(a) : "memory");
    asm volatile("ld.shared.v2.b64 {%0,%1}, [%2+48];" : "=l"(v[6]), "=l"(v[7]) : "r"(a) : "memory");
}

__device__ __forceinline__ float dot16r(const u64* v, const u64* w){
    u64 s0 = fmul2(v[0], w[0]);
    u64 s1 = fmul2(v[1], w[1]);
    u64 s2 = fmul2(v[2], w[2]);
    u64 s3 = fmul2(v[3], w[3]);
    s0 = ffma2(v[4], w[4], s0);
    s1 = ffma2(v[5], w[5], s1);
    s2 = ffma2(v[6], w[6], s2);
    s3 = ffma2(v[7], w[7], s3);
    u64 t0 = fadd2(s0, s1);
    u64 t1 = fadd2(s2, s3);
    u64 t2 = fadd2(t0, t1);
    float2 f = unpk2(t2);
    return f.x + f.y;
}
__device__ __forceinline__ float sum16r(const u64* v){
    u64 t0 = fadd2(v[0], v[1]);
    u64 t1 = fadd2(v[2], v[3]);
    u64 t2 = fadd2(v[4], v[5]);
    u64 t3 = fadd2(v[6], v[7]);
    u64 t4 = fadd2(t0, t1);
    u64 t5 = fadd2(t2, t3);
    u64 t6 = fadd2(t4, t5);
    float2 f = unpk2(t6);
    return f.x + f.y;
}

__device__ __forceinline__ void load_row16(const float* __restrict__ base, u64* wp){
    const float4* p = (const float4*)base;
#pragma unroll
    for (int k = 0; k < 4; ++k) {
        float4 f = p[k];
        wp[2*k]   = pk2(f.x, f.y);
        wp[2*k+1] = pk2(f.z, f.w);
    }
}

// GRU whh rows live in shared: stride 68 floats (=272B, 16B-aligned) so the
// 16 per-lane row starts hit distinct banks (17*l mod 32 all distinct).
#define WHH_ROW_STRIDE 68
#define WHH_GATE_STRIDE (16*WHH_ROW_STRIDE)

__global__ void __launch_bounds__(32) ode_rnn_kernel(
    const float* __restrict__ x_seq,
    const float* __restrict__ w1, const float* __restrict__ b1,
    const float* __restrict__ w2, const float* __restrict__ b2,
    const float* __restrict__ w3, const float* __restrict__ b3,
    const float* __restrict__ gwih, const float* __restrict__ gwhh,
    const float* __restrict__ gb,  const float* __restrict__ gbn,
    const float* __restrict__ pw,  const float* __restrict__ pb,
    float* __restrict__ out)
{
    const int lane = threadIdx.x;
    const int l = lane & 15;          // hidden component
    const int s = lane >> 4;          // sample within warp (0/1)
    const int b = blockIdx.x * 2 + s;

    // per-sample slots (64B each): 0/1 ping-pong, 2 G(y_new), 3 H(gru|rh2), 4 R(rh1)
    __shared__ __align__(16) float sbuf[160];
    __shared__ __align__(16) float w3s[16*16];
    __shared__ __align__(16) float whh_s[3*WHH_GATE_STRIDE];

    const unsigned base_a = (unsigned)__cvta_generic_to_shared(sbuf) + s * 320u;
    unsigned cur_a = base_a;
    unsigned alt_a = base_a + 64u;
    const unsigned G_a = base_a + 128u;
    const unsigned H_a = base_a + 192u;
    const unsigned R_a = base_a + 256u;

    // per-lane shared addresses of this lane's three GRU rows
    const unsigned whh_base = (unsigned)__cvta_generic_to_shared(whh_s);
    const unsigned whr_a = whh_base + (unsigned)(l * WHH_ROW_STRIDE) * 4u;
    const unsigned whz_a = whr_a + (unsigned)WHH_GATE_STRIDE * 4u;
    const unsigned whn_a = whz_a + (unsigned)WHH_GATE_STRIDE * 4u;

    u64 w1p[8], w2p[8], w3p[8];
    load_row16(w1 + l*16, w1p);
    load_row16(w2 + l*16, w2p);
    load_row16(w3 + l*16, w3p);
    const float b1s = b1[l] * TWO_LOG2E;
    const float b2s = b2[l] * TWO_LOG2E;
    const float b3v = b3[l];
    const float wr0 = gwih[l*2],      wr1 = gwih[l*2+1];
    const float wz0 = gwih[(16+l)*2], wz1 = gwih[(16+l)*2+1];
    const float wn0 = gwih[(32+l)*2], wn1 = gwih[(32+l)*2+1];
    const float gbr = gb[l], gbz = gb[16+l], gbnn = gb[32+l];
    const float bnv = gbn[l];
    const float pwv = pw[l];
    const float pbv = pb[0];

    // ---- stage GRU whh rows into shared (values bit-identical to before) ----
    if (s == 0) {
#pragma unroll
        for (int g = 0; g < 3; ++g) {
            const float4* src = (const float4*)(gwhh + (g*16 + l)*16);
            float* dst = whh_s + g*WHH_GATE_STRIDE + l*WHH_ROW_STRIDE;
            float4 f0 = src[0], f1 = src[1], f2 = src[2], f3 = src[3];
            ((float4*)dst)[0] = f0; ((float4*)dst)[1] = f1;
            ((float4*)dst)[2] = f2; ((float4*)dst)[3] = f3;
        }
    }
    __syncwarp();

    // ---- one-time precompute: w13 = w1 @ w3 (row l), w1b3 = (w1 @ b3)[l] ----
    if (s == 0) {
        float4* dst = (float4*)(w3s + l*16);
        const float4* srcp = (const float4*)(w3 + l*16);
        dst[0] = srcp[0]; dst[1] = srcp[1]; dst[2] = srcp[2]; dst[3] = srcp[3];
    }
    __syncwarp();
    u64 w13p[8];
#pragma unroll
    for (int i = 0; i < 8; ++i) w13p[i] = 0ull;
#pragma unroll
    for (int j = 0; j < 16; ++j) {
        float2 pr = unpk2(w1p[j >> 1]);
        float c = (j & 1) ? pr.y : pr.x;
        u64 cc = pk2(c, c);
        const ulonglong2* r = (const ulonglong2*)(w3s + j*16);
        ulonglong2 r0 = r[0], r1 = r[1], r2 = r[2], r3 = r[3];
        w13p[0] = ffma2(cc, r0.x, w13p[0]);
        w13p[1] = ffma2(cc, r0.y, w13p[1]);
        w13p[2] = ffma2(cc, r1.x, w13p[2]);
        w13p[3] = ffma2(cc, r1.y, w13p[3]);
        w13p[4] = ffma2(cc, r2.x, w13p[4]);
        w13p[5] = ffma2(cc, r2.y, w13p[5]);
        w13p[6] = ffma2(cc, r3.x, w13p[6]);
        w13p[7] = ffma2(cc, r3.y, w13p[7]);
    }
    float w1b3v;
    {
        u64 b3q[8];
        load_row16(b3, b3q);
        w1b3v = dot16r(b3q, w1p);
    }
    __syncwarp();

#define SWAPA { unsigned _t = cur_a; cur_a = alt_a; alt_a = _t; }
    // uout (forward-critical) issues BEFORE kout (off-chain).
#define F_EVAL2(z1, kout, uout) do {                                        \
        float _h1 = tanh_pre((z1), b1s);                                    \
        sts32(cur_a + (unsigned)(l*4), _h1);                                \
        u64 _v[8]; lds_v16(cur_a, _v); SWAPA;                               \
        float _h2 = tanh_pre(dot16r(_v, w2p), b2s);                         \
        sts32(cur_a + (unsigned)(l*4), _h2);                                \
        u64 _w[8]; lds_v16(cur_a, _w); SWAPA;                               \
        uout = dot16r(_w, w13p) + w1b3v;                                    \
        kout = dot16r(_w, w3p) + b3v;                                       \
    } while (0)

    // -------- unified per-half state machine --------
    const float2* xb2 = (const float2*)(x_seq + (size_t)b * (TSEQ*2));
    int   ts  = 0;
    int   itc = 0;
    float t = 0.0f, dt = 1.0f;
    float y = 0.0f, w1y = 0.0f;

    float2 xv = xb2[0];
    float ir  = fmaf(xv.x, wr0, fmaf(xv.y, wr1, gbr));
    float iz  = fmaf(xv.x, wz0, fmaf(xv.y, wz1, gbz));
    float inn = fmaf(xv.x, wn0, fmaf(xv.y, wn1, gbnn));

    float k1, u1;
    F_EVAL2(0.0f, k1, u1);    // seed at y0 = 0

#pragma unroll 1
    for (;;) {
        float dt_c = fminf(dt, 1.0f - t);

        float a, k2,u2, k3,u3, k4,u4, k5,u5, k6,u6;
        a = 0.161f * u1;
        F_EVAL2(fmaf(dt_c, a, w1y), k2, u2);
        a = fmaf(0.335480655492357f, u2, -0.008480655492356989f * u1);
        F_EVAL2(fmaf(dt_c, a, w1y), k3, u3);
        a = 2.8971530571054935f * u1;
        a = fmaf(-6.359448489975075f, u2, a);
        a = fmaf(4.3622954328695815f, u3, a);
        F_EVAL2(fmaf(dt_c, a, w1y), k4, u4);
        a = 5.325864828439257f * u1;
        a = fmaf(-11.748883564062828f, u2, a);
        a = fmaf(7.4955393428898365f, u3, a);
        a = fmaf(-0.09249506636175525f, u4, a);
        F_EVAL2(fmaf(dt_c, a, w1y), k5, u5);
        a = 5.86145544294642f * u1;
        a = fmaf(-12.92096931784711f, u2, a);
        a = fmaf(8.159367898576159f, u3, a);
        a = fmaf(-0.071584973281401f, u4, a);
        a = fmaf(-0.028269050394068383f, u5, a);
        F_EVAL2(fmaf(dt_c, a, w1y), k6, u6);

        a = 0.09646076681806523f * u1;
        a = fmaf(0.01f, u2, a);
        a = fmaf(0.4798896504144996f, u3, a);
        a = fmaf(1.379008574103742f, u4, a);
        a = fmaf(-3.290069515436081f, u5, a);
        a = fmaf(2.324710524099774f, u6, a);
        float w1y_new = fmaf(dt_c, a, w1y);
        a = 0.09646076681806523f * k1;
        a = fmaf(0.01f, k2, a);
        a = fmaf(0.4798896504144996f, k3, a);
        a = fmaf(1.379008574103742f, k4, a);
        a = fmaf(-3.290069515436081f, k5, a);
        a = fmaf(2.324710524099774f, k6, a);
        float y_new = fmaf(dt_c, a, y);

        float errp = -0.001780011052225777f * k1;
        errp = fmaf(-0.0008164344596567469f, k2, errp);
        errp = fmaf(0.007880878010261995f, k3, errp);
        errp = fmaf(-0.1447110071732629f, k4, errp);
        errp = fmaf(0.5823571654525552f, k5, errp);
        errp = fmaf(-0.45808210592918697f, k6, errp);
        float scale = fmaf(0.01f, fmaxf(fabsf(y), fabsf(y_new)), 0.0001f);
        float rscale = rcpa(scale);

        // ---- k7 eval with speculative GRU(y_new) hand-interleaved ----
        sts32(G_a + (unsigned)(l*4), y_new);        // broadcast y_new early
        u64 gv[8]; lds_v16(G_a, gv);
        u64 wrr[8]; lds_v16(whr_a, wrr);            // GRU rows: issue with gv
        u64 wzz[8]; lds_v16(whz_a, wzz);
        u64 wnn[8]; lds_v16(whn_a, wnn);
        float _h1 = tanh_pre(w1y_new, b1s);
        sts32(cur_a + (unsigned)(l*4), _h1);
        u64 _v[8]; lds_v16(cur_a, _v); SWAPA;
        float hrA = dot16r(gv, wrr);
        float hzA = dot16r(gv, wzz);
        float hnA = dot16r(gv, wnn);
        float _h2 = tanh_pre(dot16r(_v, w2p), b2s);
        float rA = fast_sigmoid(ir + hrA);
        float zA = fast_sigmoid(iz + hzA);
        float nA = fast_tanh(fmaf(rA, hnA + bnv, inn));
        float gruA = nA + zA * (y_new - nA);
        sts32(H_a + (unsigned)(l*4), gruA);         // broadcast gru(y_new)
        u64 hv[8]; lds_v16(H_a, hv);
        sts32(cur_a + (unsigned)(l*4), _h2);
        u64 _w[8]; lds_v16(cur_a, _w); SWAPA;
        float w1gA = dot16r(hv, w1p);               // fin-critical first
        float u7 = dot16r(_w, w13p) + w1b3v;
        float k7 = dot16r(_w, w3p) + b3v;

        // ---- reseed eval TEXTUALLY WOVEN with err-reduce + controller ----
        float rh1 = tanh_pre(w1gA, b1s);                        // reseed s1
        float err = dt_c * fmaf(0.015151515151515152f, k7, errp); // err chain
        float q = err * rscale;
        float e = q * q;
        sts32(R_a + (unsigned)(l*4), rh1);
        sts32(cur_a + (unsigned)(l*4), e);
        u64 rv[8]; lds_v16(R_a, rv);
        u64 ev[8]; lds_v16(cur_a, ev); SWAPA;
        float d2r = dot16r(rv, w2p);                            // reseed s2 dot
        float err2 = fmaxf(sum16r(ev) * 0.0625f, 1e-16f);       // err reduce
        float rh2 = tanh_pre(d2r, b2s);
        float factor = fminf(fmaxf(0.9f * ex2a(-0.1f * lg2a(err2)), 0.2f), 10.0f);
        sts32(H_a + (unsigned)(l*4), rh2);                      // reuse H slot
        u64 r2v[8]; lds_v16(H_a, r2v);
        // bookkeeping in the stall gap of the final reseed hop
        const bool active = (ts < TSEQ);
        bool accept = (err2 <= 1.0f) && active;
        float t1 = accept ? (t + dt_c) : t;
        float dt1 = dt_c * factor;
        itc += 1;
        bool fin = ((t1 >= 1.0f) || (itc >= 16)) && active;
        bool fin_acc = fin && accept;
        bool slow    = fin && !accept;
        float usA = dot16r(r2v, w13p) + w1b3v;                  // on-chain first
        float ksA = dot16r(r2v, w3p) + b3v;

        // defaults (!fin): FSAL continue / reject
        float y_nx   = accept ? y_new   : y;
        float w1y_nx = accept ? w1y_new : w1y;
        float k1_nx  = accept ? k7 : k1;
        float u1_nx  = accept ? u7 : u1;
        // fin&&accept: speculative GRU + reseed results
        y_nx   = fin_acc ? gruA : y_nx;
        w1y_nx = fin_acc ? w1gA : w1y_nx;
        k1_nx  = fin_acc ? ksA  : k1_nx;
        u1_nx  = fin_acc ? usA  : u1_nx;

        if (__builtin_expect(__any_sync(FULLM, slow), 0)) {
            // serial GRU(y) + reseed for cap-terminated halves (bit-exact)
            sts32(cur_a + (unsigned)(l*4), y);
            u64 sv[8]; lds_v16(cur_a, sv); SWAPA;
            u64 wr2[8]; lds_v16(whr_a, wr2);
            u64 wz2[8]; lds_v16(whz_a, wz2);
            u64 wn2[8]; lds_v16(whn_a, wn2);
            float hrS = dot16r(sv, wr2);
            float hzS = dot16r(sv, wz2);
            float hnS = dot16r(sv, wn2);
            float rS = fast_sigmoid(ir + hrS);
            float zS = fast_sigmoid(iz + hzS);
            float nS = fast_tanh(fmaf(rS, hnS + bnv, inn));
            float gruS = nS + zS * (y - nS);
            sts32(cur_a + (unsigned)(l*4), gruS);
            u64 s2v[8]; lds_v16(cur_a, s2v); SWAPA;
            float w1gS = dot16r(s2v, w1p);
            float ksS, usS;
            F_EVAL2(w1gS, ksS, usS);
            y_nx   = slow ? gruS : y_nx;
            w1y_nx = slow ? w1gS : w1y_nx;
            k1_nx  = slow ? ksS  : k1_nx;
            u1_nx  = slow ? usS  : u1_nx;
        }

        y = y_nx; w1y = w1y_nx; k1 = k1_nx; u1 = u1_nx;
        t   = fin ? 0.0f : t1;
        dt  = fin ? 1.0f : dt1;
        itc = fin ? 0 : itc;
        ts += fin ? 1 : 0;

        if (__all_sync(FULLM, ts >= TSEQ)) break;

        int tsc = (ts < TSEQ) ? ts : (TSEQ - 1);
        xv = xb2[tsc];
        ir  = fmaf(xv.x, wr0, fmaf(xv.y, wr1, gbr));
        iz  = fmaf(xv.x, wz0, fmaf(xv.y, wz1, gbz));
        inn = fmaf(xv.x, wn0, fmaf(xv.y, wn1, gbnn));
    }

    // ---- prediction head (reduce within each 16-lane half) ----
    float v = y * pwv;
    v += __shfl_xor_sync(FULLM, v, 8, 16);
    v += __shfl_xor_sync(FULLM, v, 4, 16);
    v += __shfl_xor_sync(FULLM, v, 2, 16);
    v += __shfl_xor_sync(FULLM, v, 1, 16);
    if (l == 0) out[b] = v + pbv;
#undef F_EVAL2
#undef SWAPA
}

extern "C" void kernel_launch(void* const* d_in, const int* in_sizes, int n_in,
                              void* d_out, int out_size) {
    (void)in_sizes; (void)n_in; (void)out_size;
    ode_rnn_kernel<<<NB/2, 32>>>(
        (const float*)d_in[0],
        (const float*)d_in[1],  (const float*)d_in[2],
        (const float*)d_in[3],  (const float*)d_in[4],
        (const float*)d_in[5],  (const float*)d_in[6],
        (const float*)d_in[7],  (const float*)d_in[8],
        (const float*)d_in[9],  (const float*)d_in[10],
        (const float*)d_in[11], (const float*)d_in[12],
        (float*)d_out);
}

// round 17
// speedup vs baseline: 1.0604x; 1.0604x over previous
#include <cuda_runtime.h>

typedef unsigned long long u64;

#define TSEQ 64
#define NB 2048
#define FULLM 0xffffffffu

// ---------------- packed fp32x2 + MUFU helpers ----------------
__device__ __forceinline__ u64 ffma2(u64 a, u64 b, u64 c) {
    u64 d; asm("fma.rn.f32x2 %0, %1, %2, %3;" : "=l"(d) : "l"(a), "l"(b), "l"(c)); return d;
}
__device__ __forceinline__ u64 fmul2(u64 a, u64 b) {
    u64 d; asm("mul.rn.f32x2 %0, %1, %2;" : "=l"(d) : "l"(a), "l"(b)); return d;
}
__device__ __forceinline__ u64 fadd2(u64 a, u64 b) {
    u64 d; asm("add.rn.f32x2 %0, %1, %2;" : "=l"(d) : "l"(a), "l"(b)); return d;
}
__device__ __forceinline__ float2 unpk2(u64 a) {
    float lo, hi; asm("mov.b64 {%0, %1}, %2;" : "=f"(lo), "=f"(hi) : "l"(a));
    return make_float2(lo, hi);
}
__device__ __forceinline__ u64 pk2(float lo, float hi) {
    u64 d; asm("mov.b64 %0, {%1, %2};" : "=l"(d) : "f"(lo), "f"(hi)); return d;
}
__device__ __forceinline__ float ex2a(float x){ float r; asm("ex2.approx.f32 %0, %1;" : "=f"(r) : "f"(x)); return r; }
__device__ __forceinline__ float rcpa(float x){ float r; asm("rcp.approx.f32 %0, %1;" : "=f"(r) : "f"(x)); return r; }
__device__ __forceinline__ float lg2a(float x){ float r; asm("lg2.approx.f32 %0, %1;" : "=f"(r) : "f"(x)); return r; }

#define TWO_LOG2E 2.885390081777927f

__device__ __forceinline__ float tanh_pre(float z, float bs){
    float e = ex2a(fmaf(z, TWO_LOG2E, bs));
    return fmaf(-2.0f, rcpa(e + 1.0f), 1.0f);
}
__device__ __forceinline__ float fast_tanh(float x){
    float e = ex2a(x * TWO_LOG2E);
    return fmaf(-2.0f, rcpa(e + 1.0f), 1.0f);
}
__device__ __forceinline__ float fast_sigmoid(float x){
    float e = ex2a(x * -1.4426950408889634f);
    return rcpa(e + 1.0f);
}

// ---- ordered smem primitives (converged-warp STS->LDS, asm-ordered) ----
__device__ __forceinline__ void sts32(unsigned a, float v){
    asm volatile("st.shared.b32 [%0], %1;" :: "r"(a), "f"(v) : "memory");
}
__device__ __forceinline__ void lds_v16(unsigned a, u64* v){
    asm volatile("ld.shared.v2.b64 {%0,%1}, [%2];"    : "=l"(v[0]), "=l"(v[1]) : "r"(a) : "memory");
    asm volatile("ld.shared.v2.b64 {%0,%1}, [%2+16];" : "=l"(v[2]), "=l"(v[3]) : "r"(a) : "memory");
    asm volatile("ld.shared.v2.b64 {%0,%1}, [%2+32];" : "=l"(v[4]), "=l"(v[5]) : "r"(a) : "memory");
    asm volatile("ld.shared.v2.b64 {%0,%1}, [%2+48];" : "=l"(v[6]), "=l"(v[7]) : "r"(a) : "memory");
}

__device__ __forceinline__ float dot16r(const u64* v, const u64* w){
    u64 s0 = fmul2(v[0], w[0]);
    u64 s1 = fmul2(v[1], w[1]);
    u64 s2 = fmul2(v[2], w[2]);
    u64 s3 = fmul2(v[3], w[3]);
    s0 = ffma2(v[4], w[4], s0);
    s1 = ffma2(v[5], w[5], s1);
    s2 = ffma2(v[6], w[6], s2);
    s3 = ffma2(v[7], w[7], s3);
    u64 t0 = fadd2(s0, s1);
    u64 t1 = fadd2(s2, s3);
    u64 t2 = fadd2(t0, t1);
    float2 f = unpk2(t2);
    return f.x + f.y;
}
__device__ __forceinline__ float sum16r(const u64* v){
    u64 t0 = fadd2(v[0], v[1]);
    u64 t1 = fadd2(v[2], v[3]);
    u64 t2 = fadd2(v[4], v[5]);
    u64 t3 = fadd2(v[6], v[7]);
    u64 t4 = fadd2(t0, t1);
    u64 t5 = fadd2(t2, t3);
    u64 t6 = fadd2(t4, t5);
    float2 f = unpk2(t6);
    return f.x + f.y;
}

__device__ __forceinline__ void load_row16(const float* __restrict__ base, u64* wp){
    const float4* p = (const float4*)base;
#pragma unroll
    for (int k = 0; k < 4; ++k) {
        float4 f = p[k];
        wp[2*k]   = pk2(f.x, f.y);
        wp[2*k+1] = pk2(f.z, f.w);
    }
}

__global__ void __launch_bounds__(32) ode_rnn_kernel(
    const float* __restrict__ x_seq,
    const float* __restrict__ w1, const float* __restrict__ b1,
    const float* __restrict__ w2, const float* __restrict__ b2,
    const float* __restrict__ w3, const float* __restrict__ b3,
    const float* __restrict__ gwih, const float* __restrict__ gwhh,
    const float* __restrict__ gb,  const float* __restrict__ gbn,
    const float* __restrict__ pw,  const float* __restrict__ pb,
    float* __restrict__ out)
{
    const int lane = threadIdx.x;
    const int l = lane & 15;          // hidden component
    const int s = lane >> 4;          // sample within warp (0/1)
    const int b = blockIdx.x * 2 + s;

    // per-sample slots (64B each): 0/1 ping-pong, 2 G(y_new), 3 H(gru|rh2), 4 R(rh1)
    __shared__ __align__(16) float sbuf[160];
    __shared__ __align__(16) float w3s[16*16];

    const unsigned base_a = (unsigned)__cvta_generic_to_shared(sbuf) + s * 320u;
    unsigned cur_a = base_a;
    unsigned alt_a = base_a + 64u;
    const unsigned G_a = base_a + 128u;
    const unsigned H_a = base_a + 192u;
    const unsigned R_a = base_a + 256u;

    u64 w1p[8], w2p[8], w3p[8], whr[8], whz[8], whn[8];
    load_row16(w1 + l*16, w1p);
    load_row16(w2 + l*16, w2p);
    load_row16(w3 + l*16, w3p);
    load_row16(gwhh + l*16,      whr);
    load_row16(gwhh + (16+l)*16, whz);
    load_row16(gwhh + (32+l)*16, whn);
    const float b1s = b1[l] * TWO_LOG2E;
    const float b2s = b2[l] * TWO_LOG2E;
    const float b3v = b3[l];
    const float wr0 = gwih[l*2],      wr1 = gwih[l*2+1];
    const float wz0 = gwih[(16+l)*2], wz1 = gwih[(16+l)*2+1];
    const float wn0 = gwih[(32+l)*2], wn1 = gwih[(32+l)*2+1];
    const float gbr = gb[l], gbz = gb[16+l], gbnn = gb[32+l];
    const float bnv = gbn[l];
    const float pwv = pw[l];
    const float pbv = pb[0];

    // ---- one-time precompute: w13 = w1 @ w3 (row l), w1b3 = (w1 @ b3)[l] ----
    if (s == 0) {
        float4* dst = (float4*)(w3s + l*16);
        const float4* srcp = (const float4*)(w3 + l*16);
        dst[0] = srcp[0]; dst[1] = srcp[1]; dst[2] = srcp[2]; dst[3] = srcp[3];
    }
    __syncwarp();
    u64 w13p[8];
#pragma unroll
    for (int i = 0; i < 8; ++i) w13p[i] = 0ull;
#pragma unroll
    for (int j = 0; j < 16; ++j) {
        float2 pr = unpk2(w1p[j >> 1]);
        float c = (j & 1) ? pr.y : pr.x;
        u64 cc = pk2(c, c);
        const ulonglong2* r = (const ulonglong2*)(w3s + j*16);
        ulonglong2 r0 = r[0], r1 = r[1], r2 = r[2], r3 = r[3];
        w13p[0] = ffma2(cc, r0.x, w13p[0]);
        w13p[1] = ffma2(cc, r0.y, w13p[1]);
        w13p[2] = ffma2(cc, r1.x, w13p[2]);
        w13p[3] = ffma2(cc, r1.y, w13p[3]);
        w13p[4] = ffma2(cc, r2.x, w13p[4]);
        w13p[5] = ffma2(cc, r2.y, w13p[5]);
        w13p[6] = ffma2(cc, r3.x, w13p[6]);
        w13p[7] = ffma2(cc, r3.y, w13p[7]);
    }
    float w1b3v;
    {
        u64 b3q[8];
        load_row16(b3, b3q);
        w1b3v = dot16r(b3q, w1p);
    }
    __syncwarp();

#define SWAPA { unsigned _t = cur_a; cur_a = alt_a; alt_a = _t; }
    // uout (forward-critical) issues BEFORE kout (off-chain).
#define F_EVAL2(z1, kout, uout) do {                                        \
        float _h1 = tanh_pre((z1), b1s);                                    \
        sts32(cur_a + (unsigned)(l*4), _h1);                                \
        u64 _v[8]; lds_v16(cur_a, _v); SWAPA;                               \
        float _h2 = tanh_pre(dot16r(_v, w2p), b2s);                         \
        sts32(cur_a + (unsigned)(l*4), _h2);                                \
        u64 _w[8]; lds_v16(cur_a, _w); SWAPA;                               \
        uout = dot16r(_w, w13p) + w1b3v;                                    \
        kout = dot16r(_w, w3p) + b3v;                                       \
    } while (0)

    // -------- unified per-half state machine --------
    const float2* xb2 = (const float2*)(x_seq + (size_t)b * (TSEQ*2));
    int   ts  = 0;
    int   itc = 0;
    float t = 0.0f, dt = 1.0f;
    float y = 0.0f, w1y = 0.0f;

    float k1, u1;
    F_EVAL2(0.0f, k1, u1);    // seed at y0 = 0

#pragma unroll 1
    for (;;) {
        float dt_c = fminf(dt, 1.0f - t);

        // issue the x-gate LDG early (non-blocking); its dependent fmafs
        // run AFTER the k2 eval so the ~40cyc load latency hides under it.
        int tsc = (ts < TSEQ) ? ts : (TSEQ - 1);
        float2 xv = xb2[tsc];

        float a, k2,u2, k3,u3, k4,u4, k5,u5, k6,u6;
        a = 0.161f * u1;
        F_EVAL2(fmaf(dt_c, a, w1y), k2, u2);

        // gates consumed only in the k7-weave far below; xv landed long ago
        float ir  = fmaf(xv.x, wr0, fmaf(xv.y, wr1, gbr));
        float iz  = fmaf(xv.x, wz0, fmaf(xv.y, wz1, gbz));
        float inn = fmaf(xv.x, wn0, fmaf(xv.y, wn1, gbnn));

        a = fmaf(0.335480655492357f, u2, -0.008480655492356989f * u1);
        F_EVAL2(fmaf(dt_c, a, w1y), k3, u3);
        a = 2.8971530571054935f * u1;
        a = fmaf(-6.359448489975075f, u2, a);
        a = fmaf(4.3622954328695815f, u3, a);
        F_EVAL2(fmaf(dt_c, a, w1y), k4, u4);
        a = 5.325864828439257f * u1;
        a = fmaf(-11.748883564062828f, u2, a);
        a = fmaf(7.4955393428898365f, u3, a);
        a = fmaf(-0.09249506636175525f, u4, a);
        F_EVAL2(fmaf(dt_c, a, w1y), k5, u5);
        a = 5.86145544294642f * u1;
        a = fmaf(-12.92096931784711f, u2, a);
        a = fmaf(8.159367898576159f, u3, a);
        a = fmaf(-0.071584973281401f, u4, a);
        a = fmaf(-0.028269050394068383f, u5, a);
        F_EVAL2(fmaf(dt_c, a, w1y), k6, u6);

        a = 0.09646076681806523f * u1;
        a = fmaf(0.01f, u2, a);
        a = fmaf(0.4798896504144996f, u3, a);
        a = fmaf(1.379008574103742f, u4, a);
        a = fmaf(-3.290069515436081f, u5, a);
        a = fmaf(2.324710524099774f, u6, a);
        float w1y_new = fmaf(dt_c, a, w1y);
        a = 0.09646076681806523f * k1;
        a = fmaf(0.01f, k2, a);
        a = fmaf(0.4798896504144996f, k3, a);
        a = fmaf(1.379008574103742f, k4, a);
        a = fmaf(-3.290069515436081f, k5, a);
        a = fmaf(2.324710524099774f, k6, a);
        float y_new = fmaf(dt_c, a, y);

        float errp = -0.001780011052225777f * k1;
        errp = fmaf(-0.0008164344596567469f, k2, errp);
        errp = fmaf(0.007880878010261995f, k3, errp);
        errp = fmaf(-0.1447110071732629f, k4, errp);
        errp = fmaf(0.5823571654525552f, k5, errp);
        errp = fmaf(-0.45808210592918697f, k6, errp);
        float scale = fmaf(0.01f, fmaxf(fabsf(y), fabsf(y_new)), 0.0001f);
        float rscale = rcpa(scale);

        // ---- k7 eval with speculative GRU(y_new) hand-interleaved ----
        sts32(G_a + (unsigned)(l*4), y_new);        // broadcast y_new early
        u64 gv[8]; lds_v16(G_a, gv);
        float _h1 = tanh_pre(w1y_new, b1s);
        sts32(cur_a + (unsigned)(l*4), _h1);
        u64 _v[8]; lds_v16(cur_a, _v); SWAPA;
        float hrA = dot16r(gv, whr);
        float hzA = dot16r(gv, whz);
        float hnA = dot16r(gv, whn);
        float _h2 = tanh_pre(dot16r(_v, w2p), b2s);
        float rA = fast_sigmoid(ir + hrA);
        float zA = fast_sigmoid(iz + hzA);
        float nA = fast_tanh(fmaf(rA, hnA + bnv, inn));
        float gruA = nA + zA * (y_new - nA);
        sts32(H_a + (unsigned)(l*4), gruA);         // broadcast gru(y_new)
        u64 hv[8]; lds_v16(H_a, hv);
        sts32(cur_a + (unsigned)(l*4), _h2);
        u64 _w[8]; lds_v16(cur_a, _w); SWAPA;
        float w1gA = dot16r(hv, w1p);               // fin-critical first
        float u7 = dot16r(_w, w13p) + w1b3v;
        float k7 = dot16r(_w, w3p) + b3v;

        // ---- reseed eval TEXTUALLY WOVEN with err-reduce + controller ----
        float rh1 = tanh_pre(w1gA, b1s);                        // reseed s1
        float err = dt_c * fmaf(0.015151515151515152f, k7, errp); // err chain
        float q = err * rscale;
        float e = q * q;
        sts32(R_a + (unsigned)(l*4), rh1);
        sts32(cur_a + (unsigned)(l*4), e);
        u64 rv[8]; lds_v16(R_a, rv);
        u64 ev[8]; lds_v16(cur_a, ev); SWAPA;
        float d2r = dot16r(rv, w2p);                            // reseed s2 dot
        float err2 = fmaxf(sum16r(ev) * 0.0625f, 1e-16f);       // err reduce
        float rh2 = tanh_pre(d2r, b2s);
        float factor = fminf(fmaxf(0.9f * ex2a(-0.1f * lg2a(err2)), 0.2f), 10.0f);
        sts32(H_a + (unsigned)(l*4), rh2);                      // reuse H slot
        u64 r2v[8]; lds_v16(H_a, r2v);
        // bookkeeping in the stall gap of the final reseed hop
        const bool active = (ts < TSEQ);
        bool accept = (err2 <= 1.0f) && active;
        float t1 = accept ? (t + dt_c) : t;
        float dt1 = dt_c * factor;
        itc += 1;
        bool fin = ((t1 >= 1.0f) || (itc >= 16)) && active;
        bool fin_acc = fin && accept;
        bool slow    = fin && !accept;
        float usA = dot16r(r2v, w13p) + w1b3v;                  // on-chain first
        float ksA = dot16r(r2v, w3p) + b3v;

        // defaults (!fin): FSAL continue / reject
        float y_nx   = accept ? y_new   : y;
        float w1y_nx = accept ? w1y_new : w1y;
        float k1_nx  = accept ? k7 : k1;
        float u1_nx  = accept ? u7 : u1;
        // fin&&accept: speculative GRU + reseed results
        y_nx   = fin_acc ? gruA : y_nx;
        w1y_nx = fin_acc ? w1gA : w1y_nx;
        k1_nx  = fin_acc ? ksA  : k1_nx;
        u1_nx  = fin_acc ? usA  : u1_nx;

        if (__builtin_expect(__any_sync(FULLM, slow), 0)) {
            // serial GRU(y) + reseed for cap-terminated halves (bit-exact)
            sts32(cur_a + (unsigned)(l*4), y);
            u64 sv[8]; lds_v16(cur_a, sv); SWAPA;
            float hrS = dot16r(sv, whr);
            float hzS = dot16r(sv, whz);
            float hnS = dot16r(sv, whn);
            float rS = fast_sigmoid(ir + hrS);
            float zS = fast_sigmoid(iz + hzS);
            float nS = fast_tanh(fmaf(rS, hnS + bnv, inn));
            float gruS = nS + zS * (y - nS);
            sts32(cur_a + (unsigned)(l*4), gruS);
            u64 s2v[8]; lds_v16(cur_a, s2v); SWAPA;
            float w1gS = dot16r(s2v, w1p);
            float ksS, usS;
            F_EVAL2(w1gS, ksS, usS);
            y_nx   = slow ? gruS : y_nx;
            w1y_nx = slow ? w1gS : w1y_nx;
            k1_nx  = slow ? ksS  : k1_nx;
            u1_nx  = slow ? usS  : u1_nx;
        }

        y = y_nx; w1y = w1y_nx; k1 = k1_nx; u1 = u1_nx;
        t   = fin ? 0.0f : t1;
        dt  = fin ? 1.0f : dt1;
        itc = fin ? 0 : itc;
        ts += fin ? 1 : 0;

        if (__all_sync(FULLM, ts >= TSEQ)) break;
    }

    // ---- prediction head (reduce within each 16-lane half) ----
    float v = y * pwv;
    v += __shfl_xor_sync(FULLM, v, 8, 16);
    v += __shfl_xor_sync(FULLM, v, 4, 16);
    v += __shfl_xor_sync(FULLM, v, 2, 16);
    v += __shfl_xor_sync(FULLM, v, 1, 16);
    if (l == 0) out[b] = v + pbv;
#undef F_EVAL2
#undef SWAPA
}

extern "C" void kernel_launch(void* const* d_in, const int* in_sizes, int n_in,
                              void* d_out, int out_size) {
    (void)in_sizes; (void)n_in; (void)out_size;
    ode_rnn_kernel<<<NB/2, 32>>>(
        (const float*)d_in[0],
        (const float*)d_in[1],  (const float*)d_in[2],
        (const float*)d_in[3],  (const float*)d_in[4],
        (const float*)d_in[5],  (const float*)d_in[6],
        (const float*)d_in[7],  (const float*)d_in[8],
        (const float*)d_in[9],  (const float*)d_in[10],
        (const float*)d_in[11], (const float*)d_in[12],
        (float*)d_out);
}